// round 4
// baseline (speedup 1.0000x reference)
#include <cuda_runtime.h>
#include <cstdint>
#include <cstddef>

// ---------------- scratch (no allocations allowed) ----------------
__device__ float  g_p[4 * 8192 * 128]; // split-K partial sums, 16 MB
__device__ float  g_o1[8192 * 128];    // selu(fc1) activations, 4 MB
__device__ float  g_csum[128];
__device__ float  g_csumsq[128];
__device__ float  g_scale[128];        // bn fused scale
__device__ float  g_shift[128];        // bn fused shift
__device__ float  g_o[8192 * 2];       // final embedding
__device__ float  g_sq[8192];          // row squared norms
__device__ double g_denom;             // sum over strict upper triangle
__device__ float  g_inv;               // 1 / (2 * g_denom)

__device__ __forceinline__ float selu_f(float v) {
    const float sc = 1.0507009873554805f;
    const float al = 1.6732632423543772f;
    return v > 0.f ? sc * v : sc * al * expm1f(v);
}

__device__ __forceinline__ float frcp(float x) {
    float r;
    asm("rcp.approx.f32 %0, %1;" : "=f"(r) : "f"(x));
    return r;
}

// ---------------- kernel 0: zero accumulators ----------------
__global__ void k_init() {
    int t = threadIdx.x;
    if (t < 128) { g_csum[t] = 0.f; g_csumsq[t] = 0.f; }
    if (t == 0)  { g_denom = 0.0; }
}

// ---------------- kernel 1: split-K partials of x @ W1^T ----------------
// M=8192, N=128, K=784 (49 chunks of 16). grid(128, 4): 64-row tiles x 4 K-slices
// K-slice y covers chunks [c0ch, c0ch+nch): 13,12,12,12.
__global__ __launch_bounds__(256) void k_gemm1(
    const float* __restrict__ x, const float* __restrict__ w)
{
    __shared__ float As[16][68];    // [k][m] transposed, padded
    __shared__ float Bs[16][132];   // [k][n] padded

    int t  = threadIdx.x;
    int tx = t & 15;       // col group (8 cols each)
    int ty = t >> 4;       // row group (4 rows each)
    int row0 = blockIdx.x * 64;
    int y    = blockIdx.y;
    int c0ch = y * 12 + (y > 0 ? 1 : 0);
    int nch  = (y == 0) ? 13 : 12;

    float acc[4][8];
#pragma unroll
    for (int i = 0; i < 4; i++)
#pragma unroll
        for (int j = 0; j < 8; j++) acc[i][j] = 0.f;

    for (int ci = 0; ci < nch; ci++) {
        int k0 = (c0ch + ci) * 16;
        // load A tile 64x16 (float4 along k, transpose into As[k][m])
        {
            int r  = t >> 2;          // 0..63
            int kk = (t & 3) * 4;     // 0,4,8,12
            float4 v = *(const float4*)&x[(size_t)(row0 + r) * 784 + k0 + kk];
            As[kk + 0][r] = v.x;
            As[kk + 1][r] = v.y;
            As[kk + 2][r] = v.z;
            As[kk + 3][r] = v.w;
        }
        // load B tile: Bs[k][n] = w[n][k],  16x128
        {
            int n  = t >> 1;          // 0..127
            int kk = (t & 1) * 8;     // 0 or 8
            float4 v0 = *(const float4*)&w[(size_t)n * 784 + k0 + kk];
            float4 v1 = *(const float4*)&w[(size_t)n * 784 + k0 + kk + 4];
            Bs[kk + 0][n] = v0.x; Bs[kk + 1][n] = v0.y;
            Bs[kk + 2][n] = v0.z; Bs[kk + 3][n] = v0.w;
            Bs[kk + 4][n] = v1.x; Bs[kk + 5][n] = v1.y;
            Bs[kk + 6][n] = v1.z; Bs[kk + 7][n] = v1.w;
        }
        __syncthreads();

#pragma unroll
        for (int k = 0; k < 16; k++) {
            float4 a  = *(const float4*)&As[k][ty * 4];
            float4 b0 = *(const float4*)&Bs[k][tx * 8];
            float4 b1 = *(const float4*)&Bs[k][tx * 8 + 4];
            float av[4] = {a.x, a.y, a.z, a.w};
            float bv[8] = {b0.x, b0.y, b0.z, b0.w, b1.x, b1.y, b1.z, b1.w};
#pragma unroll
            for (int i = 0; i < 4; i++)
#pragma unroll
                for (int j = 0; j < 8; j++)
                    acc[i][j] = fmaf(av[i], bv[j], acc[i][j]);
        }
        __syncthreads();
    }

    int col = tx * 8;
#pragma unroll
    for (int i = 0; i < 4; i++) {
        int row = row0 + ty * 4 + i;
        size_t base = ((size_t)y * 8192 + row) * 128 + col;
        *(float4*)&g_p[base]     = make_float4(acc[i][0], acc[i][1], acc[i][2], acc[i][3]);
        *(float4*)&g_p[base + 4] = make_float4(acc[i][4], acc[i][5], acc[i][6], acc[i][7]);
    }
}

// ---------------- kernel 2: o1 = selu(sum partials + b1), fused stats ----------------
// grid 128 blocks x 256 threads; block covers 64 rows; thread = (rowhalf, channel)
__global__ __launch_bounds__(256) void k_combine(const float* __restrict__ bias) {
    int t  = threadIdx.x;
    int c  = t & 127;
    int rh = t >> 7;
    int r0 = blockIdx.x * 64 + rh * 32;
    float b = bias[c];

    float s = 0.f, ss = 0.f;
    for (int r = 0; r < 32; r++) {
        size_t idx = (size_t)(r0 + r) * 128 + c;
        float v = g_p[idx] + g_p[idx + 8192u * 128u]
                + g_p[idx + 2u * 8192u * 128u] + g_p[idx + 3u * 8192u * 128u] + b;
        v = selu_f(v);
        g_o1[idx] = v;
        s += v;
        ss = fmaf(v, v, ss);
    }

    __shared__ float red_s[2][128], red_q[2][128];
    red_s[rh][c] = s;
    red_q[rh][c] = ss;
    __syncthreads();
    if (t < 128) {
        atomicAdd(&g_csum[t],   red_s[0][t] + red_s[1][t]);
        atomicAdd(&g_csumsq[t], red_q[0][t] + red_q[1][t]);
    }
}

// ---------------- kernel 3: finalize BN scale/shift ----------------
__global__ void k_stats_final(const float* __restrict__ gamma,
                              const float* __restrict__ beta) {
    int c = threadIdx.x;
    const float invn = 1.f / 8192.f;
    float mu  = g_csum[c] * invn;
    float var = g_csumsq[c] * invn - mu * mu;
    float rstd = rsqrtf(var + 1e-5f);
    float sc = rstd * gamma[c];
    g_scale[c] = sc;
    g_shift[c] = beta[c] - mu * sc;
}

// ---------------- kernel 4: o = selu(bn(o1) @ W2^T + b2), sq ----------------
__global__ __launch_bounds__(256) void k_fc2(
    const float* __restrict__ w2, const float* __restrict__ b2,
    float* __restrict__ o_tail)
{
    int gw   = (blockIdx.x * blockDim.x + threadIdx.x) >> 5;  // warp id = row
    int lane = threadIdx.x & 31;
    if (gw >= 8192) return;

    float a0 = 0.f, a1 = 0.f;
#pragma unroll
    for (int q = 0; q < 4; q++) {
        int c = lane + q * 32;
        float v = fmaf(g_o1[(size_t)gw * 128 + c], g_scale[c], g_shift[c]);
        a0 = fmaf(v, w2[c], a0);
        a1 = fmaf(v, w2[128 + c], a1);
    }
#pragma unroll
    for (int off = 16; off > 0; off >>= 1) {
        a0 += __shfl_xor_sync(0xffffffffu, a0, off);
        a1 += __shfl_xor_sync(0xffffffffu, a1, off);
    }
    if (lane == 0) {
        float y0 = selu_f(a0 + b2[0]);
        float y1 = selu_f(a1 + b2[1]);
        g_o[2 * gw]     = y0;
        g_o[2 * gw + 1] = y1;
        g_sq[gw] = fmaf(y1, y1, y0 * y0);
        o_tail[2 * gw]     = y0;
        o_tail[2 * gw + 1] = y1;
    }
}

// ---------------- kernel 5: denom = sum over strict upper triangle ----------------
// tile: 64 rows x 2048 cols. grid(4, 128). Each thread owns 8 contiguous cols
// (kept in registers); only the 64 row points go to smem.
__global__ __launch_bounds__(256) void k_denom() {
    int c0 = blockIdx.x * 2048;
    int i0 = blockIdx.y * 64;
    if (c0 + 2047 <= i0) return;          // whole tile at/below diagonal

    __shared__ float srx[64], sry[64], srq[64];
    int t = threadIdx.x;
    if (t < 64) {
        srx[t] = g_o[2 * (i0 + t)];
        sry[t] = g_o[2 * (i0 + t) + 1];
        srq[t] = g_sq[i0 + t];
    }

    // this thread's 8 columns -> registers
    int cbase = c0 + t * 8;
    float cx[8], cy[8], cq[8];
    {
        const float4* o4 = (const float4*)g_o;
#pragma unroll
        for (int q = 0; q < 4; q++) {
            float4 v = o4[(cbase >> 1) + q];
            cx[2 * q] = v.x;  cy[2 * q] = v.y;
            cx[2 * q + 1] = v.z;  cy[2 * q + 1] = v.w;
        }
        const float4* s4 = (const float4*)g_sq;
        float4 q0 = s4[cbase >> 2], q1 = s4[(cbase >> 2) + 1];
        cq[0] = q0.x; cq[1] = q0.y; cq[2] = q0.z; cq[3] = q0.w;
        cq[4] = q1.x; cq[5] = q1.y; cq[6] = q1.z; cq[7] = q1.w;
    }
    __syncthreads();

    float lsum = 0.f;
    if (c0 > i0 + 63) {
        // strictly upper: no predicate needed
#pragma unroll 4
        for (int r = 0; r < 64; r++) {
            float xi = srx[r], yi = sry[r], si = srq[r];
#pragma unroll
            for (int j = 0; j < 8; j++) {
                float dot = fmaf(yi, cy[j], xi * cx[j]);
                float w   = fmaf(-2.f, dot, si + cq[j]);
                w = fmaxf(w, 0.f) + 1.f;
                lsum += frcp(w);
            }
        }
    } else {
        // diagonal-crossing tile: predicated
#pragma unroll 4
        for (int r = 0; r < 64; r++) {
            int i = i0 + r;
            float xi = srx[r], yi = sry[r], si = srq[r];
#pragma unroll
            for (int j = 0; j < 8; j++) {
                float dot = fmaf(yi, cy[j], xi * cx[j]);
                float w   = fmaf(-2.f, dot, si + cq[j]);
                w = fmaxf(w, 0.f) + 1.f;
                float v = frcp(w);
                if (cbase + j > i) lsum += v;
            }
        }
    }

    __shared__ float red[256];
    red[t] = lsum;
    __syncthreads();
    for (int s = 128; s > 0; s >>= 1) {
        if (t < s) red[t] += red[t + s];
        __syncthreads();
    }
    if (t == 0) atomicAdd(&g_denom, (double)red[0]);
}

// ---------------- kernel 6: inv denom ----------------
__global__ void k_inv() {
    g_inv = (float)(1.0 / (2.0 * g_denom));
}

// ---------------- kernel 7: write qij ----------------
// tile: 32 rows x 2048 cols. grid(4, 256). Cols in registers, rows in smem.
__global__ __launch_bounds__(256) void k_write(float* __restrict__ out) {
    int c0 = blockIdx.x * 2048;
    int i0 = blockIdx.y * 32;

    __shared__ float srx[32], sry[32], srq[32];
    int t = threadIdx.x;
    if (t < 32) {
        srx[t] = g_o[2 * (i0 + t)];
        sry[t] = g_o[2 * (i0 + t) + 1];
        srq[t] = g_sq[i0 + t];
    }

    int cbase = c0 + t * 8;
    float cx[8], cy[8], cq[8];
    {
        const float4* o4 = (const float4*)g_o;
#pragma unroll
        for (int q = 0; q < 4; q++) {
            float4 v = o4[(cbase >> 1) + q];
            cx[2 * q] = v.x;  cy[2 * q] = v.y;
            cx[2 * q + 1] = v.z;  cy[2 * q + 1] = v.w;
        }
        const float4* s4 = (const float4*)g_sq;
        float4 q0 = s4[cbase >> 2], q1 = s4[(cbase >> 2) + 1];
        cq[0] = q0.x; cq[1] = q0.y; cq[2] = q0.z; cq[3] = q0.w;
        cq[4] = q1.x; cq[5] = q1.y; cq[6] = q1.z; cq[7] = q1.w;
    }
    __syncthreads();

    float inv = g_inv;

#pragma unroll 2
    for (int r = 0; r < 32; r++) {
        float xi = srx[r], yi = sry[r], si = srq[r];
        float q[8];
#pragma unroll
        for (int j = 0; j < 8; j++) {
            float dot = fmaf(yi, cy[j], xi * cx[j]);
            float w   = fmaf(-2.f, dot, si + cq[j]);
            w = fmaxf(w, 0.f) + 1.f;
            q[j] = inv * frcp(w);
        }
        float* dst = &out[(size_t)(i0 + r) * 8192 + cbase];
        // streaming stores: qij is never re-read, keep it out of L2
        asm volatile("st.global.cs.v4.f32 [%0], {%1, %2, %3, %4};"
                     :: "l"(dst), "f"(q[0]), "f"(q[1]), "f"(q[2]), "f"(q[3])
                     : "memory");
        asm volatile("st.global.cs.v4.f32 [%0], {%1, %2, %3, %4};"
                     :: "l"(dst + 4), "f"(q[4]), "f"(q[5]), "f"(q[6]), "f"(q[7])
                     : "memory");
    }
}

// ---------------- launch ----------------
extern "C" void kernel_launch(void* const* d_in, const int* in_sizes, int n_in,
                              void* d_out, int out_size) {
    const float* x     = (const float*)d_in[0];
    const float* fc_w  = (const float*)d_in[1];
    const float* fc_b  = (const float*)d_in[2];
    const float* gamma = (const float*)d_in[3];
    const float* beta  = (const float*)d_in[4];
    const float* fc2_w = (const float*)d_in[5];
    const float* fc2_b = (const float*)d_in[6];
    float* out = (float*)d_out;
    // output layout: qij [8192*8192] then o [8192*2]
    float* o_tail = out + ((size_t)out_size - 8192 * 2);

    k_init<<<1, 256>>>();
    k_gemm1<<<dim3(128, 4), 256>>>(x, fc_w);
    k_combine<<<128, 256>>>(fc_b);
    k_stats_final<<<1, 128>>>(gamma, beta);
    k_fc2<<<1024, 256>>>(fc2_w, fc2_b, o_tail);
    k_denom<<<dim3(4, 128), 256>>>();
    k_inv<<<1, 1>>>();
    k_write<<<dim3(4, 256), 256>>>(out);
}

// round 5
// speedup vs baseline: 1.1309x; 1.1309x over previous
#include <cuda_runtime.h>
#include <cstdint>
#include <cstddef>

// ---------------- scratch (no allocations allowed) ----------------
__device__ float  g_o1[8192 * 128];    // selu(fc1) activations, 4 MB
__device__ float  g_csum[128];
__device__ float  g_csumsq[128];
__device__ float  g_scale[128];        // bn fused scale
__device__ float  g_shift[128];        // bn fused shift
__device__ float  g_o[8192 * 2];       // final embedding
__device__ float  g_sq[8192];          // row squared norms
__device__ double g_denom;             // sum over strict upper triangle
__device__ float  g_inv;               // 1 / (2 * g_denom)

__device__ __forceinline__ float selu_f(float v) {
    const float sc = 1.0507009873554805f;
    const float al = 1.6732632423543772f;
    return v > 0.f ? sc * v : sc * al * expm1f(v);
}

__device__ __forceinline__ float frcp(float x) {
    float r;
    asm("rcp.approx.f32 %0, %1;" : "=f"(r) : "f"(x));
    return r;
}

// ---------------- kernel 0: zero accumulators ----------------
__global__ void k_init() {
    int t = threadIdx.x;
    if (t < 128) { g_csum[t] = 0.f; g_csumsq[t] = 0.f; }
    if (t == 0)  { g_denom = 0.0; }
}

// ---------------- kernel 1: o1 = selu(x @ W1^T + b1), fused BN stats ------
// M=8192, N=128, K=784 (49 chunks of 16). grid=128, 64x128 tile, 4x8/thread.
// Software-pipelined: prefetch next chunk into registers during compute.
__global__ __launch_bounds__(256) void k_gemm1(
    const float* __restrict__ x, const float* __restrict__ w,
    const float* __restrict__ bias)
{
    __shared__ float As[16][68];    // [k][m] transposed, padded
    __shared__ float Bs[16][132];   // [k][n] padded
    __shared__ float s_sum[128], s_ssq[128];

    int t  = threadIdx.x;
    int tx = t & 15;       // col group (8 cols each)
    int ty = t >> 4;       // row group (4 rows each)
    int row0 = blockIdx.x * 64;

    if (t < 128) { s_sum[t] = 0.f; s_ssq[t] = 0.f; }

    // per-thread fixed load addresses (advance by k0 each chunk)
    int ar  = t >> 2;              // 0..63 : A row within tile
    int akk = (t & 3) * 4;         // 0,4,8,12 : A k offset
    const float* aPtr = &x[(size_t)(row0 + ar) * 784 + akk];
    int bn  = t >> 1;              // 0..127 : B row (output channel)
    int bkk = (t & 1) * 8;         // 0 or 8 : B k offset
    const float* bPtr = &w[(size_t)bn * 784 + bkk];

    float acc[4][8];
#pragma unroll
    for (int i = 0; i < 4; i++)
#pragma unroll
        for (int j = 0; j < 8; j++) acc[i][j] = 0.f;

    // prologue: prefetch chunk 0
    float4 aReg  = *(const float4*)(aPtr);
    float4 bRegA = *(const float4*)(bPtr);
    float4 bRegB = *(const float4*)(bPtr + 4);

    const int NCH = 49;
    for (int ci = 0; ci < NCH; ci++) {
        // stage registers -> smem
        As[akk + 0][ar] = aReg.x;
        As[akk + 1][ar] = aReg.y;
        As[akk + 2][ar] = aReg.z;
        As[akk + 3][ar] = aReg.w;
        Bs[bkk + 0][bn] = bRegA.x; Bs[bkk + 1][bn] = bRegA.y;
        Bs[bkk + 2][bn] = bRegA.z; Bs[bkk + 3][bn] = bRegA.w;
        Bs[bkk + 4][bn] = bRegB.x; Bs[bkk + 5][bn] = bRegB.y;
        Bs[bkk + 6][bn] = bRegB.z; Bs[bkk + 7][bn] = bRegB.w;
        __syncthreads();

        // prefetch next chunk (LDG in flight during compute below)
        if (ci + 1 < NCH) {
            int k0 = (ci + 1) * 16;
            aReg  = *(const float4*)(aPtr + k0);
            bRegA = *(const float4*)(bPtr + k0);
            bRegB = *(const float4*)(bPtr + k0 + 4);
        }

#pragma unroll
        for (int k = 0; k < 16; k++) {
            float4 a  = *(const float4*)&As[k][ty * 4];
            float4 b0 = *(const float4*)&Bs[k][tx * 8];
            float4 b1 = *(const float4*)&Bs[k][tx * 8 + 4];
            float av[4] = {a.x, a.y, a.z, a.w};
            float bv[8] = {b0.x, b0.y, b0.z, b0.w, b1.x, b1.y, b1.z, b1.w};
#pragma unroll
            for (int i = 0; i < 4; i++)
#pragma unroll
                for (int j = 0; j < 8; j++)
                    acc[i][j] = fmaf(av[i], bv[j], acc[i][j]);
        }
        __syncthreads();
    }

    // epilogue: bias + selu, store o1, accumulate BN stats
    int col = tx * 8;
    float bias8[8];
#pragma unroll
    for (int j = 0; j < 8; j++) bias8[j] = bias[col + j];

    float colsum[8], colssq[8];
#pragma unroll
    for (int j = 0; j < 8; j++) { colsum[j] = 0.f; colssq[j] = 0.f; }

#pragma unroll
    for (int i = 0; i < 4; i++) {
        int row = row0 + ty * 4 + i;
        float v[8];
#pragma unroll
        for (int j = 0; j < 8; j++) {
            v[j] = selu_f(acc[i][j] + bias8[j]);
            colsum[j] += v[j];
            colssq[j] = fmaf(v[j], v[j], colssq[j]);
        }
        *(float4*)&g_o1[(size_t)row * 128 + col]     = make_float4(v[0], v[1], v[2], v[3]);
        *(float4*)&g_o1[(size_t)row * 128 + col + 4] = make_float4(v[4], v[5], v[6], v[7]);
    }

#pragma unroll
    for (int j = 0; j < 8; j++) {
        atomicAdd(&s_sum[col + j], colsum[j]);
        atomicAdd(&s_ssq[col + j], colssq[j]);
    }
    __syncthreads();
    if (t < 128) {
        atomicAdd(&g_csum[t],   s_sum[t]);
        atomicAdd(&g_csumsq[t], s_ssq[t]);
    }
}

// ---------------- kernel 2: finalize BN scale/shift ----------------
__global__ void k_stats_final(const float* __restrict__ gamma,
                              const float* __restrict__ beta) {
    int c = threadIdx.x;
    const float invn = 1.f / 8192.f;
    float mu  = g_csum[c] * invn;
    float var = g_csumsq[c] * invn - mu * mu;
    float rstd = rsqrtf(var + 1e-5f);
    float sc = rstd * gamma[c];
    g_scale[c] = sc;
    g_shift[c] = beta[c] - mu * sc;
}

// ---------------- kernel 3: o = selu(bn(o1) @ W2^T + b2), sq ----------------
__global__ __launch_bounds__(256) void k_fc2(
    const float* __restrict__ w2, const float* __restrict__ b2,
    float* __restrict__ o_tail)
{
    int gw   = (blockIdx.x * blockDim.x + threadIdx.x) >> 5;  // warp id = row
    int lane = threadIdx.x & 31;
    if (gw >= 8192) return;

    int c = lane * 4;
    float4 v4 = *(const float4*)&g_o1[(size_t)gw * 128 + c];
    float4 sc = *(const float4*)&g_scale[c];
    float4 sh = *(const float4*)&g_shift[c];
    float4 w0 = *(const float4*)&w2[c];
    float4 w1 = *(const float4*)&w2[128 + c];

    float vx = fmaf(v4.x, sc.x, sh.x);
    float vy = fmaf(v4.y, sc.y, sh.y);
    float vz = fmaf(v4.z, sc.z, sh.z);
    float vw = fmaf(v4.w, sc.w, sh.w);

    float a0 = fmaf(vx, w0.x, fmaf(vy, w0.y, fmaf(vz, w0.z, vw * w0.w)));
    float a1 = fmaf(vx, w1.x, fmaf(vy, w1.y, fmaf(vz, w1.z, vw * w1.w)));

#pragma unroll
    for (int off = 16; off > 0; off >>= 1) {
        a0 += __shfl_xor_sync(0xffffffffu, a0, off);
        a1 += __shfl_xor_sync(0xffffffffu, a1, off);
    }
    if (lane == 0) {
        float y0 = selu_f(a0 + b2[0]);
        float y1 = selu_f(a1 + b2[1]);
        g_o[2 * gw]     = y0;
        g_o[2 * gw + 1] = y1;
        g_sq[gw] = fmaf(y1, y1, y0 * y0);
        o_tail[2 * gw]     = y0;
        o_tail[2 * gw + 1] = y1;
    }
}

// ---------------- kernel 4: denom = sum over strict upper triangle ----------
// tile: 64 rows x 2048 cols. grid(4, 128). Each thread owns 8 contiguous cols
// (kept in registers); only the 64 row points go to smem.
__global__ __launch_bounds__(256) void k_denom() {
    int c0 = blockIdx.x * 2048;
    int i0 = blockIdx.y * 64;
    if (c0 + 2047 <= i0) return;          // whole tile at/below diagonal

    __shared__ float srx[64], sry[64], srq[64];
    int t = threadIdx.x;
    if (t < 64) {
        srx[t] = g_o[2 * (i0 + t)];
        sry[t] = g_o[2 * (i0 + t) + 1];
        srq[t] = g_sq[i0 + t];
    }

    int cbase = c0 + t * 8;
    float cx[8], cy[8], cq[8];
    {
        const float4* o4 = (const float4*)g_o;
#pragma unroll
        for (int q = 0; q < 4; q++) {
            float4 v = o4[(cbase >> 1) + q];
            cx[2 * q] = v.x;      cy[2 * q] = v.y;
            cx[2 * q + 1] = v.z;  cy[2 * q + 1] = v.w;
        }
        const float4* s4 = (const float4*)g_sq;
        float4 q0 = s4[cbase >> 2], q1 = s4[(cbase >> 2) + 1];
        cq[0] = q0.x; cq[1] = q0.y; cq[2] = q0.z; cq[3] = q0.w;
        cq[4] = q1.x; cq[5] = q1.y; cq[6] = q1.z; cq[7] = q1.w;
    }
    __syncthreads();

    float lsum = 0.f;
    if (c0 > i0 + 63) {
        // strictly upper: predicate-free
#pragma unroll 4
        for (int r = 0; r < 64; r++) {
            float xi = srx[r], yi = sry[r], si = srq[r];
#pragma unroll
            for (int j = 0; j < 8; j++) {
                float dot = fmaf(yi, cy[j], xi * cx[j]);
                float w   = fmaf(-2.f, dot, si + cq[j]);
                w = fmaxf(w, 0.f) + 1.f;
                lsum += frcp(w);
            }
        }
    } else {
        // diagonal-crossing tile: predicated
#pragma unroll 4
        for (int r = 0; r < 64; r++) {
            int i = i0 + r;
            float xi = srx[r], yi = sry[r], si = srq[r];
#pragma unroll
            for (int j = 0; j < 8; j++) {
                float dot = fmaf(yi, cy[j], xi * cx[j]);
                float w   = fmaf(-2.f, dot, si + cq[j]);
                w = fmaxf(w, 0.f) + 1.f;
                float v = frcp(w);
                if (cbase + j > i) lsum += v;
            }
        }
    }

    __shared__ float red[256];
    red[t] = lsum;
    __syncthreads();
    for (int s = 128; s > 0; s >>= 1) {
        if (t < s) red[t] += red[t + s];
        __syncthreads();
    }
    if (t == 0) atomicAdd(&g_denom, (double)red[0]);
}

// ---------------- kernel 5: inv denom ----------------
__global__ void k_inv() {
    g_inv = (float)(1.0 / (2.0 * g_denom));
}

// ---------------- kernel 6: write qij ----------------
// tile: 32 rows x 2048 cols. grid(4, 256). Cols in registers, rows in smem.
__global__ __launch_bounds__(256) void k_write(float* __restrict__ out) {
    int c0 = blockIdx.x * 2048;
    int i0 = blockIdx.y * 32;

    __shared__ float srx[32], sry[32], srq[32];
    int t = threadIdx.x;
    if (t < 32) {
        srx[t] = g_o[2 * (i0 + t)];
        sry[t] = g_o[2 * (i0 + t) + 1];
        srq[t] = g_sq[i0 + t];
    }

    int cbase = c0 + t * 8;
    float cx[8], cy[8], cq[8];
    {
        const float4* o4 = (const float4*)g_o;
#pragma unroll
        for (int q = 0; q < 4; q++) {
            float4 v = o4[(cbase >> 1) + q];
            cx[2 * q] = v.x;      cy[2 * q] = v.y;
            cx[2 * q + 1] = v.z;  cy[2 * q + 1] = v.w;
        }
        const float4* s4 = (const float4*)g_sq;
        float4 q0 = s4[cbase >> 2], q1 = s4[(cbase >> 2) + 1];
        cq[0] = q0.x; cq[1] = q0.y; cq[2] = q0.z; cq[3] = q0.w;
        cq[4] = q1.x; cq[5] = q1.y; cq[6] = q1.z; cq[7] = q1.w;
    }
    __syncthreads();

    float inv = g_inv;

#pragma unroll 2
    for (int r = 0; r < 32; r++) {
        float xi = srx[r], yi = sry[r], si = srq[r];
        float q[8];
#pragma unroll
        for (int j = 0; j < 8; j++) {
            float dot = fmaf(yi, cy[j], xi * cx[j]);
            float w   = fmaf(-2.f, dot, si + cq[j]);
            w = fmaxf(w, 0.f) + 1.f;
            q[j] = inv * frcp(w);
        }
        float* dst = &out[(size_t)(i0 + r) * 8192 + cbase];
        // streaming stores: qij is never re-read, keep it out of L2
        asm volatile("st.global.cs.v4.f32 [%0], {%1, %2, %3, %4};"
                     :: "l"(dst), "f"(q[0]), "f"(q[1]), "f"(q[2]), "f"(q[3])
                     : "memory");
        asm volatile("st.global.cs.v4.f32 [%0], {%1, %2, %3, %4};"
                     :: "l"(dst + 4), "f"(q[4]), "f"(q[5]), "f"(q[6]), "f"(q[7])
                     : "memory");
    }
}

// ---------------- launch ----------------
extern "C" void kernel_launch(void* const* d_in, const int* in_sizes, int n_in,
                              void* d_out, int out_size) {
    const float* x     = (const float*)d_in[0];
    const float* fc_w  = (const float*)d_in[1];
    const float* fc_b  = (const float*)d_in[2];
    const float* gamma = (const float*)d_in[3];
    const float* beta  = (const float*)d_in[4];
    const float* fc2_w = (const float*)d_in[5];
    const float* fc2_b = (const float*)d_in[6];
    float* out = (float*)d_out;
    // output layout: qij [8192*8192] then o [8192*2]
    float* o_tail = out + ((size_t)out_size - 8192 * 2);

    k_init<<<1, 256>>>();
    k_gemm1<<<128, 256>>>(x, fc_w, fc_b);
    k_stats_final<<<1, 128>>>(gamma, beta);
    k_fc2<<<1024, 256>>>(fc2_w, fc2_b, o_tail);
    k_denom<<<dim3(4, 128), 256>>>();
    k_inv<<<1, 1>>>();
    k_write<<<dim3(4, 256), 256>>>(out);
}